// round 1
// baseline (speedup 1.0000x reference)
#include <cuda_runtime.h>

#define NN 30000
#define NE 480000
#define HID 128
#define F_IN 64
#define F_EDGE 16
#define NCLS 10

// ---------------- device scratch (no allocations allowed) ----------------
__device__ __align__(16) float g_ea[(size_t)NE * HID];   // dst-sorted edge encodings (245.8 MB)
__device__ int   g_perm[NE];
__device__ int   g_srcs[NE];                              // dst-sorted src ids
__device__ int   g_rowptr[NN + 1];
__device__ int   g_cnt[NN];
__device__ __align__(16) float g_h[NN * HID];             // running node features
__device__ __align__(16) float g_nin[NN * HID];           // conv input (prenormed)
__device__ __align__(16) float g_agg[NN * HID];
__device__ __align__(16) float g_mid[NN * 2 * HID];

// ---------------- CSR build ----------------
__global__ void k_zero_cnt() {
    int i = blockIdx.x * blockDim.x + threadIdx.x;
    if (i < NN) g_cnt[i] = 0;
}

__global__ void k_hist(const int* __restrict__ dst) {
    int i = blockIdx.x * blockDim.x + threadIdx.x;
    if (i < NE) atomicAdd(&g_cnt[dst[i]], 1);
}

__global__ __launch_bounds__(1024) void k_scan() {
    __shared__ int wsum[32];
    const int CH = 30;  // 1024*30 = 30720 >= NN
    int tid = threadIdx.x;
    int base = tid * CH;
    int s = 0;
#pragma unroll
    for (int i = 0; i < CH; i++) {
        int idx = base + i;
        if (idx < NN) s += g_cnt[idx];
    }
    int lane = tid & 31, wid = tid >> 5;
    int v = s;
#pragma unroll
    for (int off = 1; off < 32; off <<= 1) {
        int t = __shfl_up_sync(0xffffffffu, v, off);
        if (lane >= off) v += t;
    }
    if (lane == 31) wsum[wid] = v;
    __syncthreads();
    if (wid == 0) {
        int wv = wsum[lane];
#pragma unroll
        for (int off = 1; off < 32; off <<= 1) {
            int t = __shfl_up_sync(0xffffffffu, wv, off);
            if (lane >= off) wv += t;
        }
        wsum[lane] = wv;
    }
    __syncthreads();
    int excl = v - s + (wid ? wsum[wid - 1] : 0);
    int run = excl;
#pragma unroll
    for (int i = 0; i < CH; i++) {
        int idx = base + i;
        if (idx < NN) {
            g_rowptr[idx] = run;
            run += g_cnt[idx];
        }
    }
    if (tid == 1023) g_rowptr[NN] = run;
}

__global__ void k_scatter(const int* __restrict__ dst) {
    int i = blockIdx.x * blockDim.x + threadIdx.x;
    if (i < NE) {
        int d = dst[i];
        int pos = g_rowptr[d] + atomicAdd(&g_cnt[d], 1);
        g_perm[pos] = i;
    }
}

// ---------------- edge encoder: ea_sorted[p] = edge_attr[perm[p]] @ W + b ----------------
__global__ __launch_bounds__(256) void k_edge_enc(
    const float* __restrict__ edge_attr, const int* __restrict__ src,
    const float* __restrict__ W, const float* __restrict__ bias)
{
    __shared__ __align__(16) float sW[F_EDGE * HID];
    __shared__ __align__(16) float sB[HID];
    for (int i = threadIdx.x; i < F_EDGE * HID; i += 256) sW[i] = W[i];
    if (threadIdx.x < HID) sB[threadIdx.x] = bias[threadIdx.x];
    __syncthreads();
    int lane = threadIdx.x & 31;
    int warp = (blockIdx.x * 256 + threadIdx.x) >> 5;
    int nw = gridDim.x * 8;
    float4 bv = ((float4*)sB)[lane];
    for (int p = warp; p < NE; p += nw) {
        int e = g_perm[p];
        if (lane == 0) g_srcs[p] = src[e];
        float a = (lane < F_EDGE) ? edge_attr[e * F_EDGE + lane] : 0.f;
        float4 acc = bv;
#pragma unroll
        for (int k = 0; k < F_EDGE; k++) {
            float ak = __shfl_sync(0xffffffffu, a, k);
            float4 w = ((const float4*)(sW + k * HID))[lane];
            acc.x = fmaf(ak, w.x, acc.x);
            acc.y = fmaf(ak, w.y, acc.y);
            acc.z = fmaf(ak, w.z, acc.z);
            acc.w = fmaf(ak, w.w, acc.w);
        }
        ((float4*)g_ea)[(size_t)p * 32 + lane] = acc;
    }
}

// ---------------- node encoder: h0 = x @ W + b ----------------
__global__ __launch_bounds__(256) void k_node_enc(
    const float* __restrict__ x, const float* __restrict__ W, const float* __restrict__ bias)
{
    __shared__ __align__(16) float sW[F_IN * HID];  // 32 KB
    __shared__ __align__(16) float sB[HID];
    for (int i = threadIdx.x; i < F_IN * HID; i += 256) sW[i] = W[i];
    if (threadIdx.x < HID) sB[threadIdx.x] = bias[threadIdx.x];
    __syncthreads();
    int lane = threadIdx.x & 31;
    int warp = (blockIdx.x * 256 + threadIdx.x) >> 5;
    int nw = gridDim.x * 8;
    float4 bv = ((float4*)sB)[lane];
    for (int n = warp; n < NN; n += nw) {
        float a0 = x[n * F_IN + lane];
        float a1 = x[n * F_IN + 32 + lane];
        float4 acc = bv;
#pragma unroll
        for (int k = 0; k < F_IN; k++) {
            float ak = __shfl_sync(0xffffffffu, (k < 32) ? a0 : a1, k & 31);
            float4 w = ((const float4*)(sW + k * HID))[lane];
            acc.x = fmaf(ak, w.x, acc.x);
            acc.y = fmaf(ak, w.y, acc.y);
            acc.z = fmaf(ak, w.z, acc.z);
            acc.w = fmaf(ak, w.w, acc.w);
        }
        ((float4*)g_h)[n * 32 + lane] = acc;
    }
}

// ---------------- pre-norm: nin = relu(LN(h, g, b)) ----------------
__global__ __launch_bounds__(256) void k_prenorm(const float* __restrict__ gmm,
                                                 const float* __restrict__ bb)
{
    int lane = threadIdx.x & 31;
    int n = (blockIdx.x * 256 + threadIdx.x) >> 5;
    if (n >= NN) return;
    float4 v = ((const float4*)g_h)[n * 32 + lane];
    float s = v.x + v.y + v.z + v.w;
    float q = v.x * v.x + v.y * v.y + v.z * v.z + v.w * v.w;
#pragma unroll
    for (int off = 16; off; off >>= 1) {
        s += __shfl_xor_sync(0xffffffffu, s, off);
        q += __shfl_xor_sync(0xffffffffu, q, off);
    }
    float m = s * (1.f / 128.f);
    float var = q * (1.f / 128.f) - m * m;
    float rstd = rsqrtf(var + 1e-5f);
    float4 g4 = ((const float4*)gmm)[lane];
    float4 b4 = ((const float4*)bb)[lane];
    float4 o;
    o.x = fmaxf((v.x - m) * rstd * g4.x + b4.x, 0.f);
    o.y = fmaxf((v.y - m) * rstd * g4.y + b4.y, 0.f);
    o.z = fmaxf((v.z - m) * rstd * g4.z + b4.z, 0.f);
    o.w = fmaxf((v.w - m) * rstd * g4.w + b4.w, 0.f);
    ((float4*)g_nin)[n * 32 + lane] = o;
}

// ---------------- edge aggregation: one-pass softmax (no max shift; msg >= 0, bounded) ----------------
__global__ __launch_bounds__(256) void k_edge_agg(int layer, const float* __restrict__ t_arr)
{
    int lane = threadIdx.x & 31;
    int n = (blockIdx.x * 256 + threadIdx.x) >> 5;
    if (n >= NN) return;
    const float* nin = (layer == 0) ? g_h : g_nin;
    float tv = t_arr[layer];
    int beg = g_rowptr[n], end = g_rowptr[n + 1];
    float4 s = make_float4(0.f, 0.f, 0.f, 0.f);
    float4 ws = make_float4(0.f, 0.f, 0.f, 0.f);
    const float4* ea4 = (const float4*)g_ea;
    const float4* nin4 = (const float4*)nin;
    for (int p = beg; p < end; p++) {
        int sn = g_srcs[p];
        float4 e = ea4[(size_t)p * 32 + lane];
        float4 hv = nin4[sn * 32 + lane];
        float m0 = fmaxf(hv.x + e.x, 0.f) + 1e-7f;
        float m1 = fmaxf(hv.y + e.y, 0.f) + 1e-7f;
        float m2 = fmaxf(hv.z + e.z, 0.f) + 1e-7f;
        float m3 = fmaxf(hv.w + e.w, 0.f) + 1e-7f;
        float e0 = __expf(m0 * tv);
        float e1 = __expf(m1 * tv);
        float e2 = __expf(m2 * tv);
        float e3 = __expf(m3 * tv);
        s.x += e0; s.y += e1; s.z += e2; s.w += e3;
        ws.x = fmaf(m0, e0, ws.x);
        ws.y = fmaf(m1, e1, ws.y);
        ws.z = fmaf(m2, e2, ws.z);
        ws.w = fmaf(m3, e3, ws.w);
    }
    float4 o;
    o.x = ws.x / (s.x + 1e-16f);
    o.y = ws.y / (s.y + 1e-16f);
    o.z = ws.z / (s.z + 1e-16f);
    o.w = ws.w / (s.w + 1e-16f);
    ((float4*)g_agg)[n * 32 + lane] = o;
}

// ---------------- GEMM1: mid = relu(LN((agg+nin) @ W1 + b1, lg, lb)), [NN,128]@[128,256] ----------------
__global__ __launch_bounds__(256) void k_gemm1(
    int layer, const float* __restrict__ W, const float* __restrict__ b,
    const float* __restrict__ lg, const float* __restrict__ lb)
{
    __shared__ __align__(16) float sA[32][33];
    __shared__ __align__(16) float sW[32][256];
    const float* nin = (layer == 0) ? g_h : g_nin;
    int tx = threadIdx.x & 31, ty = threadIdx.x >> 5;
    int row0 = blockIdx.x * 32;
    float acc[4][8];
#pragma unroll
    for (int i = 0; i < 4; i++)
#pragma unroll
        for (int j = 0; j < 8; j++) acc[i][j] = 0.f;

    for (int kc = 0; kc < HID; kc += 32) {
#pragma unroll
        for (int i = 0; i < 4; i++) {
            int idx = threadIdx.x + i * 256;
            int r = idx >> 5, k = idx & 31;
            int n = row0 + r;
            float v = 0.f;
            if (n < NN) v = g_agg[n * HID + kc + k] + nin[n * HID + kc + k];
            sA[r][k] = v;
        }
#pragma unroll
        for (int i = 0; i < 8; i++) {
            int idx = threadIdx.x + i * 256;  // float4 units over 32x256
            int kk = idx >> 6, c4 = idx & 63;
            ((float4*)sW[kk])[c4] = ((const float4*)(W + (kc + kk) * 256))[c4];
        }
        __syncthreads();
#pragma unroll
        for (int k = 0; k < 32; k++) {
            float a0 = sA[ty * 4 + 0][k], a1 = sA[ty * 4 + 1][k];
            float a2 = sA[ty * 4 + 2][k], a3 = sA[ty * 4 + 3][k];
#pragma unroll
            for (int j = 0; j < 8; j++) {
                float w = sW[k][tx + 32 * j];
                acc[0][j] = fmaf(a0, w, acc[0][j]);
                acc[1][j] = fmaf(a1, w, acc[1][j]);
                acc[2][j] = fmaf(a2, w, acc[2][j]);
                acc[3][j] = fmaf(a3, w, acc[3][j]);
            }
        }
        __syncthreads();
    }
    float bias[8], gg[8], bb2[8];
#pragma unroll
    for (int j = 0; j < 8; j++) {
        int c = tx + 32 * j;
        bias[j] = b[c]; gg[j] = lg[c]; bb2[j] = lb[c];
    }
#pragma unroll
    for (int i = 0; i < 4; i++) {
        float sum = 0.f, sq = 0.f;
#pragma unroll
        for (int j = 0; j < 8; j++) {
            acc[i][j] += bias[j];
            sum += acc[i][j];
            sq = fmaf(acc[i][j], acc[i][j], sq);
        }
#pragma unroll
        for (int off = 16; off; off >>= 1) {
            sum += __shfl_xor_sync(0xffffffffu, sum, off);
            sq += __shfl_xor_sync(0xffffffffu, sq, off);
        }
        float m = sum * (1.f / 256.f);
        float var = sq * (1.f / 256.f) - m * m;
        float rstd = rsqrtf(var + 1e-5f);
        int n = row0 + ty * 4 + i;
        if (n < NN) {
#pragma unroll
            for (int j = 0; j < 8; j++) {
                float val = (acc[i][j] - m) * rstd * gg[j] + bb2[j];
                g_mid[n * 256 + tx + 32 * j] = fmaxf(val, 0.f);
            }
        }
    }
}

// ---------------- GEMM2: h = mid @ W2 + b2 (+ residual h), [NN,256]@[256,128] ----------------
__global__ __launch_bounds__(256) void k_gemm2(
    const float* __restrict__ W, const float* __restrict__ b, int use_res)
{
    __shared__ __align__(16) float sA[64][33];
    __shared__ __align__(16) float sW[32][128];
    int tx = threadIdx.x & 31, ty = threadIdx.x >> 5;
    int row0 = blockIdx.x * 64;
    float acc[8][4];
#pragma unroll
    for (int i = 0; i < 8; i++)
#pragma unroll
        for (int j = 0; j < 4; j++) acc[i][j] = 0.f;

    for (int kc = 0; kc < 256; kc += 32) {
#pragma unroll
        for (int i = 0; i < 8; i++) {
            int idx = threadIdx.x + i * 256;
            int r = idx >> 5, k = idx & 31;
            int n = row0 + r;
            sA[r][k] = (n < NN) ? g_mid[n * 256 + kc + k] : 0.f;
        }
#pragma unroll
        for (int i = 0; i < 4; i++) {
            int idx = threadIdx.x + i * 256;  // float4 units over 32x128
            int kk = idx >> 5, c4 = idx & 31;
            ((float4*)sW[kk])[c4] = ((const float4*)(W + (kc + kk) * 128))[c4];
        }
        __syncthreads();
#pragma unroll
        for (int k = 0; k < 32; k++) {
            float a[8];
#pragma unroll
            for (int i = 0; i < 8; i++) a[i] = sA[ty * 8 + i][k];
#pragma unroll
            for (int j = 0; j < 4; j++) {
                float w = sW[k][tx + 32 * j];
#pragma unroll
                for (int i = 0; i < 8; i++) acc[i][j] = fmaf(a[i], w, acc[i][j]);
            }
        }
        __syncthreads();
    }
    float bias[4];
#pragma unroll
    for (int j = 0; j < 4; j++) bias[j] = b[tx + 32 * j];
#pragma unroll
    for (int i = 0; i < 8; i++) {
        int n = row0 + ty * 8 + i;
        if (n < NN) {
#pragma unroll
            for (int j = 0; j < 4; j++) {
                int c = tx + 32 * j;
                float v = acc[i][j] + bias[j];
                if (use_res) v += g_h[n * HID + c];
                g_h[n * HID + c] = v;
            }
        }
    }
}

// ---------------- classifier: out = relu(LN(h, g0, b0)) @ lin_w + lin_b ----------------
__global__ __launch_bounds__(256) void k_classifier(
    const float* __restrict__ gmm, const float* __restrict__ bb,
    const float* __restrict__ lw, const float* __restrict__ lbias,
    float* __restrict__ out)
{
    int lane = threadIdx.x & 31;
    int n = (blockIdx.x * 256 + threadIdx.x) >> 5;
    if (n >= NN) return;
    float4 v = ((const float4*)g_h)[n * 32 + lane];
    float s = v.x + v.y + v.z + v.w;
    float q = v.x * v.x + v.y * v.y + v.z * v.z + v.w * v.w;
#pragma unroll
    for (int off = 16; off; off >>= 1) {
        s += __shfl_xor_sync(0xffffffffu, s, off);
        q += __shfl_xor_sync(0xffffffffu, q, off);
    }
    float m = s * (1.f / 128.f);
    float var = q * (1.f / 128.f) - m * m;
    float rstd = rsqrtf(var + 1e-5f);
    float4 g4 = ((const float4*)gmm)[lane];
    float4 b4 = ((const float4*)bb)[lane];
    float h0 = fmaxf((v.x - m) * rstd * g4.x + b4.x, 0.f);
    float h1 = fmaxf((v.y - m) * rstd * g4.y + b4.y, 0.f);
    float h2 = fmaxf((v.z - m) * rstd * g4.z + b4.z, 0.f);
    float h3 = fmaxf((v.w - m) * rstd * g4.w + b4.w, 0.f);
    int c0 = lane * 4;
    float r[NCLS];
#pragma unroll
    for (int j = 0; j < NCLS; j++) {
        float p = h0 * lw[c0 * NCLS + j];
        p = fmaf(h1, lw[(c0 + 1) * NCLS + j], p);
        p = fmaf(h2, lw[(c0 + 2) * NCLS + j], p);
        p = fmaf(h3, lw[(c0 + 3) * NCLS + j], p);
#pragma unroll
        for (int off = 16; off; off >>= 1) p += __shfl_xor_sync(0xffffffffu, p, off);
        r[j] = p;
    }
#pragma unroll
    for (int j = 0; j < NCLS; j++)
        if (lane == j) out[n * NCLS + j] = r[j] + lbias[j];
}

// ---------------- launch ----------------
extern "C" void kernel_launch(void* const* d_in, const int* in_sizes, int n_in,
                              void* d_out, int out_size)
{
    const float* x         = (const float*)d_in[0];
    const float* edge_attr = (const float*)d_in[1];
    const float* node_w    = (const float*)d_in[2];
    const float* node_b    = (const float*)d_in[3];
    const float* edge_w    = (const float*)d_in[4];
    const float* edge_b    = (const float*)d_in[5];
    const float* mlp1_w    = (const float*)d_in[6];
    const float* mlp1_b    = (const float*)d_in[7];
    const float* ln_g      = (const float*)d_in[8];
    const float* ln_b      = (const float*)d_in[9];
    const float* mlp2_w    = (const float*)d_in[10];
    const float* mlp2_b    = (const float*)d_in[11];
    const float* t         = (const float*)d_in[12];
    const float* norm_g    = (const float*)d_in[13];
    const float* norm_b    = (const float*)d_in[14];
    const float* lin_w     = (const float*)d_in[15];
    const float* lin_b     = (const float*)d_in[16];
    const int*   edge_index= (const int*)d_in[17];
    const int* src = edge_index;
    const int* dst = edge_index + NE;
    float* out = (float*)d_out;

    // CSR build (dst-sorted edge order)
    k_zero_cnt<<<(NN + 255) / 256, 256>>>();
    k_hist<<<(NE + 255) / 256, 256>>>(dst);
    k_scan<<<1, 1024>>>();
    k_zero_cnt<<<(NN + 255) / 256, 256>>>();
    k_scatter<<<(NE + 255) / 256, 256>>>(dst);

    // encoders
    k_edge_enc<<<1184, 256>>>(edge_attr, src, edge_w, edge_b);
    k_node_enc<<<1184, 256>>>(x, node_w, node_b);

    for (int l = 0; l < 3; l++) {
        if (l > 0)
            k_prenorm<<<(NN * 32 + 255) / 256, 256>>>(norm_g + l * HID, norm_b + l * HID);
        k_edge_agg<<<(NN * 32 + 255) / 256, 256>>>(l, t);
        k_gemm1<<<(NN + 31) / 32, 256>>>(l, mlp1_w + l * HID * 2 * HID, mlp1_b + l * 2 * HID,
                                         ln_g + l * 2 * HID, ln_b + l * 2 * HID);
        k_gemm2<<<(NN + 63) / 64, 256>>>(mlp2_w + l * 2 * HID * HID, mlp2_b + l * HID, l > 0);
    }
    k_classifier<<<(NN * 32 + 255) / 256, 256>>>(norm_g, norm_b, lin_w, lin_b, out);
}